// round 16
// baseline (speedup 1.0000x reference)
#include <cuda_runtime.h>
#include <cuda_fp16.h>
#include <cstdint>

#define BB 2
#define NN 65536
#define CC 96
#define HH 3
#define HD 32
#define NG 256
#define GS 256
// ATTN_SCALE * log2(e): logits pre-scaled so softmax uses exp2 (exact)
#define ATTN_SCALE_LOG2E 0.25503837160174146f

// ---------------- fp16 mma.sync + ldmatrix + cp.async helpers ----------------
__device__ __forceinline__ uint32_t smem_u32(const void* p) {
    uint32_t a;
    asm("{ .reg .u64 t; cvta.to.shared.u64 t, %1; cvt.u32.u64 %0, t; }"
        : "=r"(a) : "l"(p));
    return a;
}
__device__ __forceinline__ void mma16h(float* d, const uint32_t* a, uint32_t b0,
                                       uint32_t b1) {
    asm volatile(
        "mma.sync.aligned.m16n8k16.row.col.f32.f16.f16.f32 "
        "{%0,%1,%2,%3}, {%4,%5,%6,%7}, {%8,%9}, {%0,%1,%2,%3};"
        : "+f"(d[0]), "+f"(d[1]), "+f"(d[2]), "+f"(d[3])
        : "r"(a[0]), "r"(a[1]), "r"(a[2]), "r"(a[3]), "r"(b0), "r"(b1));
}
__device__ __forceinline__ void ldsm4(uint32_t* r, uint32_t addr) {
    asm volatile(
        "ldmatrix.sync.aligned.m8n8.x4.shared.b16 {%0,%1,%2,%3}, [%4];"
        : "=r"(r[0]), "=r"(r[1]), "=r"(r[2]), "=r"(r[3]) : "r"(addr));
}
__device__ __forceinline__ void ldsm4t(uint32_t* r, uint32_t addr) {
    asm volatile(
        "ldmatrix.sync.aligned.m8n8.x4.trans.shared.b16 {%0,%1,%2,%3}, [%4];"
        : "=r"(r[0]), "=r"(r[1]), "=r"(r[2]), "=r"(r[3]) : "r"(addr));
}
__device__ __forceinline__ void cp_async16(uint32_t saddr, const void* gptr) {
    asm volatile("cp.async.ca.shared.global [%0], [%1], 16;"
                 :: "r"(saddr), "l"(gptr));
}
#define CP_COMMIT() asm volatile("cp.async.commit_group;" ::: "memory")
#define CP_WAIT1()  asm volatile("cp.async.wait_group 1;" ::: "memory")
#define CP_WAIT0()  asm volatile("cp.async.wait_group 0;" ::: "memory")

// ---------------- scratch -----------------------------------------------------
static __device__ __half g_qh[(size_t)BB * HH * NN * HD];
static __device__ __half g_kh[(size_t)BB * HH * NN * HD];
static __device__ __half g_vh[(size_t)BB * HH * NN * HD];
static __device__ __half g_atth[(size_t)BB * NN * CC];
static __device__ int    g_idx[(size_t)BB * NN];
static __device__ int    g_cnt2[(size_t)BB * 256 * NG];  // [b][chunk][label]

// ---------------- stable counting sort: atomic-free ---------------------------
__global__ void sortA_kernel(const int* __restrict__ vor, int b) {  // grid 256
    int blk = blockIdx.x;
    int i = threadIdx.x;
    __shared__ int hist[256];
    hist[i] = 0;
    __syncthreads();
    int l = vor[b * NN + blk * 256 + i];
    int g = min(max(l - 1, 0), 255);
    atomicAdd(&hist[g], 1);  // smem only
    __syncthreads();
    g_cnt2[(b * 256 + blk) * NG + i] = hist[i];
}

__global__ void sortB_kernel(const int* __restrict__ vor) {  // grid (256, BB)
    int b = blockIdx.y;
    int blk = blockIdx.x;
    int i = threadIdx.x;
    __shared__ int sc[256];
    __shared__ int offarr[256];
    __shared__ int lab[256];

    int tot = 0, pre = 0;
    const int* cb = g_cnt2 + b * 256 * NG + i;
#pragma unroll 4
    for (int ch = 0; ch < 256; ch++) {
        int c = cb[ch * NG];
        tot += c;
        pre += (ch < blk) ? c : 0;
    }
    sc[i] = tot;
    __syncthreads();
    for (int d = 1; d < 256; d <<= 1) {
        int t = (i >= d) ? sc[i - d] : 0;
        __syncthreads();
        sc[i] += t;
        __syncthreads();
    }
    offarr[i] = (sc[i] - tot) + pre;
    __syncthreads();

    int n = blk * 256 + i;
    int l = vor[b * NN + n];
    int g = min(max(l - 1, 0), 255);
    lab[i] = g;
    __syncthreads();
    int rank = 0;
    for (int j = 0; j < i; j++) rank += (lab[j] == g);
    g_idx[b * NN + offarr[g] + rank] = n;
}

// ---------------- persistent pipelined QKV projection ------------------------
// 128 threads, 4 warps; tile = 128 rows, warp = 32 rows. W loaded once
// (unscaled; q scale in epilogue). X fp32 cp.async'd in 32-row chunks through
// 2 stages (prefetch distance 2 chunks); owner-computes fp32->fp16 convert.
#define XH 104
#define WH 104
#define WBYTES (96 * WH * 2)               // 19968
#define Q_S0   WBYTES                      // 32x96 fp32 = 12288 B
#define Q_S1   (Q_S0 + 32 * 96 * 4)
#define Q_X    (Q_S1 + 32 * 96 * 4)
#define Q_TOTAL (Q_X + 128 * XH * 2)       // 71168 B -> 3 CTAs/SM

__global__ void __launch_bounds__(128)
proj_qkv_kernel(const float* __restrict__ x0, const float* __restrict__ x1,
                const float* __restrict__ x2, const float* __restrict__ W,
                const float* __restrict__ bias) {
    extern __shared__ char smc[];
    __half* wsm = (__half*)smc;
    __half* xsm = (__half*)(smc + Q_X);
    __shared__ float bs[96];

    int tid = threadIdx.x;
    int lane = tid & 31, wid = tid >> 5;
    int lr = lane >> 2, lc = lane & 3;

    for (int i = tid; i < 96 * 24; i += 128) {
        int k = i / 24, n4 = (i % 24) * 4;
        float4 v = *(const float4*)(W + k * 96 + n4);
        __half2 h0 = __floats2half2_rn(v.x, v.y);
        __half2 h1 = __floats2half2_rn(v.z, v.w);
        uint2 u;
        u.x = *(uint32_t*)&h0;
        u.y = *(uint32_t*)&h1;
        *(uint2*)(wsm + k * WH + n4) = u;
    }
    if (tid < 96) bs[tid] = bias[tid];

    int m0 = wid * 32;
    int tsel = lane >> 3, trow = lane & 7;
    uint32_t waddr = smem_u32(wsm) +
                     2u * (((tsel & 1) * 8 + trow) * WH + (tsel >> 1) * 8);
    uint32_t xaddr = smem_u32(xsm) +
                     2u * (((tsel & 1) * 8 + trow) * XH + (tsel >> 1) * 8);
    uint32_t st[2] = {smem_u32(smc + Q_S0), smem_u32(smc + Q_S1)};
    int stride = gridDim.x;
    const int nt = 3 * 1024;

    // per-thread chunk-copy coords (32 rows x 96 floats, 6x16B per thread)
    int pr = tid / 24 + 0, pc4 = (tid % 24) * 4;  // base; k adds 128/24 rows

    // prefetch chunk (tile, h) -> stage s
    auto prefetch = [&](int tile, int h, int s) {
        int sel = tile >> 10;
        const float* xp = (sel == 0) ? x0 : (sel == 1) ? x1 : x2;
        long rowb = (long)(tile & 1023) * 128 + h * 32;
        uint32_t sb = st[s];
#pragma unroll
        for (int k = 0; k < 6; k++) {
            int i = tid + k * 128;
            int r = i / 24, c4 = (i % 24) * 4;
            cp_async16(sb + (uint32_t)(r * 96 + c4) * 4u,
                       xp + (rowb + r) * 96 + c4);
        }
        CP_COMMIT();
    };
    (void)pr; (void)pc4;

    // prologue: first two chunks of first tile
    prefetch(blockIdx.x, 0, 0);
    prefetch(blockIdx.x, 1, 1);

    for (int t = blockIdx.x; t < nt; t += stride) {
        int tn = t + stride;
        if (tn >= nt) tn = t;  // clamp: identical-byte reissue (benign)
        __syncthreads();       // xsm free (prev epilogue reads done)

#pragma unroll
        for (int h = 0; h < 4; h++) {
            CP_WAIT1();  // oldest group (this chunk) complete
            const float* stf = (const float*)(smc + (h & 1 ? Q_S1 : Q_S0));
#pragma unroll
            for (int k = 0; k < 6; k++) {
                int i = tid + k * 128;
                int r = i / 24, c4 = (i % 24) * 4;
                float4 v = *(const float4*)(stf + r * 96 + c4);
                __half2 h0 = __floats2half2_rn(v.x, v.y);
                __half2 h1 = __floats2half2_rn(v.z, v.w);
                uint2 u;
                u.x = *(uint32_t*)&h0;
                u.y = *(uint32_t*)&h1;
                *(uint2*)(xsm + (h * 32 + r) * XH + c4) = u;
            }
            // prefetch chunk cur+2 into the same stage
            if (h < 2) prefetch(t, h + 2, h & 1);
            else       prefetch(tn, h - 2, h & 1);
        }
        __syncthreads();  // converts visible to all warps

        float acc[2][12][4];
#pragma unroll
        for (int mt = 0; mt < 2; mt++)
#pragma unroll
            for (int nn = 0; nn < 12; nn++)
#pragma unroll
                for (int j = 0; j < 4; j++) acc[mt][nn][j] = 0.f;
#pragma unroll
        for (int ks = 0; ks < 6; ks++) {
            uint32_t a[2][4];
            ldsm4(a[0], xaddr + 2u * (uint32_t)((m0 + 0) * XH + ks * 16));
            ldsm4(a[1], xaddr + 2u * (uint32_t)((m0 + 16) * XH + ks * 16));
#pragma unroll
            for (int ntp = 0; ntp < 6; ntp++) {
                uint32_t bf[4];
                ldsm4t(bf, waddr + 2u * (uint32_t)(ks * 16 * WH + ntp * 16));
                mma16h(acc[0][2 * ntp], a[0], bf[0], bf[1]);
                mma16h(acc[0][2 * ntp + 1], a[0], bf[2], bf[3]);
                mma16h(acc[1][2 * ntp], a[1], bf[0], bf[1]);
                mma16h(acc[1][2 * ntp + 1], a[1], bf[2], bf[3]);
            }
        }
        __syncthreads();  // all ldmatrix reads of xsm done

        int selc = t >> 10;
        float sc = (selc == 0) ? ATTN_SCALE_LOG2E : 1.f;
#pragma unroll
        for (int mt = 0; mt < 2; mt++)
#pragma unroll
            for (int half = 0; half < 2; half++) {
                int row = m0 + mt * 16 + lr + half * 8;
#pragma unroll
                for (int nn = 0; nn < 12; nn++) {
                    int col = nn * 8 + 2 * lc;
                    *(__half2*)(xsm + row * XH + col) = __floats2half2_rn(
                        (acc[mt][nn][half * 2 + 0] + bs[col]) * sc,
                        (acc[mt][nn][half * 2 + 1] + bs[col + 1]) * sc);
                }
            }
        __syncthreads();
        __half* dst = (selc == 0) ? g_qh : (selc == 1) ? g_kh : g_vh;
        long row0 = (long)(t & 1023) * 128;
        int bb = (int)(row0 >> 16);
        int part = tid & 3;
        int rbase = tid >> 2;
#pragma unroll
        for (int h = 0; h < 3; h++) {
            __half* hb = dst +
                ((((long)(bb * HH + h)) * NN + (row0 & (NN - 1))) * HD);
#pragma unroll
            for (int pass = 0; pass < 4; pass++) {
                int row = pass * 32 + rbase;
                *(uint4*)(hb + (long)row * HD + part * 8) =
                    *(uint4*)(xsm + row * XH + h * 32 + part * 8);
            }
        }
    }
    CP_WAIT0();
}

// ---------------- persistent pipelined output projection ----------------------
#define O_X0   WBYTES
#define O_X1   (O_X0 + 128 * XH * 2)
#define O_TOTAL (O_X1 + 128 * XH * 2)      // 73216 B -> 3 CTAs/SM

__global__ void __launch_bounds__(128)
proj_out_kernel(const float* __restrict__ W, const float* __restrict__ bias,
                float* __restrict__ extout) {
    extern __shared__ char smc[];
    __half* wsm = (__half*)smc;
    __shared__ float bs[96];

    int tid = threadIdx.x;
    int lane = tid & 31, wid = tid >> 5;
    int lr = lane >> 2, lc = lane & 3;

    for (int i = tid; i < 96 * 24; i += 128) {
        int k = i / 24, n4 = (i % 24) * 4;
        float4 v = *(const float4*)(W + k * 96 + n4);
        __half2 h0 = __floats2half2_rn(v.x, v.y);
        __half2 h1 = __floats2half2_rn(v.z, v.w);
        uint2 u;
        u.x = *(uint32_t*)&h0;
        u.y = *(uint32_t*)&h1;
        *(uint2*)(wsm + k * WH + n4) = u;
    }
    if (tid < 96) bs[tid] = bias[tid];

    int m0 = wid * 32;
    int tsel = lane >> 3, trow = lane & 7;
    uint32_t waddr = smem_u32(wsm) +
                     2u * (((tsel & 1) * 8 + trow) * WH + (tsel >> 1) * 8);
    uint32_t xb[2] = {smem_u32(smc + O_X0), smem_u32(smc + O_X1)};
    int stride = gridDim.x;
    const int nt = 1024;

#pragma unroll
    for (int p = 0; p < 2; p++) {
        int tile = blockIdx.x + p * stride;
        if (tile >= nt) tile = blockIdx.x;
        long rowb = (long)tile * 128;
#pragma unroll
        for (int k = 0; k < 12; k++) {
            int i = tid + k * 128;
            int r = i / 12, c8 = (i % 12) * 8;
            cp_async16(xb[p] + (uint32_t)(r * XH + c8) * 2u,
                       g_atth + (rowb + r) * 96 + c8);
        }
        CP_COMMIT();
    }

    int buf = 0;
    for (int t = blockIdx.x; t < nt; t += stride) {
        CP_WAIT1();
        __syncthreads();
        uint32_t xaddr = xb[buf] +
                         2u * (((tsel & 1) * 8 + trow) * XH + (tsel >> 1) * 8);

        float acc[2][12][4];
#pragma unroll
        for (int mt = 0; mt < 2; mt++)
#pragma unroll
            for (int nn = 0; nn < 12; nn++)
#pragma unroll
                for (int j = 0; j < 4; j++) acc[mt][nn][j] = 0.f;
#pragma unroll
        for (int ks = 0; ks < 6; ks++) {
            uint32_t a[2][4];
            ldsm4(a[0], xaddr + 2u * (uint32_t)((m0 + 0) * XH + ks * 16));
            ldsm4(a[1], xaddr + 2u * (uint32_t)((m0 + 16) * XH + ks * 16));
#pragma unroll
            for (int ntp = 0; ntp < 6; ntp++) {
                uint32_t bf[4];
                ldsm4t(bf, waddr + 2u * (uint32_t)(ks * 16 * WH + ntp * 16));
                mma16h(acc[0][2 * ntp], a[0], bf[0], bf[1]);
                mma16h(acc[0][2 * ntp + 1], a[0], bf[2], bf[3]);
                mma16h(acc[1][2 * ntp], a[1], bf[0], bf[1]);
                mma16h(acc[1][2 * ntp + 1], a[1], bf[2], bf[3]);
            }
        }

        long row0 = (long)t * 128;
#pragma unroll
        for (int mt = 0; mt < 2; mt++)
#pragma unroll
            for (int half = 0; half < 2; half++) {
                int row = m0 + mt * 16 + lr + half * 8;
                long gr = row0 + row;
#pragma unroll
                for (int nn = 0; nn < 12; nn++) {
                    int col = nn * 8 + 2 * lc;
                    *(float2*)(extout + gr * 96 + col) =
                        make_float2(acc[mt][nn][half * 2 + 0] + bs[col],
                                    acc[mt][nn][half * 2 + 1] + bs[col + 1]);
                }
            }
        __syncthreads();  // all reads of xb[buf] done before refill

        int tn2 = t + 2 * stride;
        if (tn2 >= nt) tn2 = t;  // clamp (identical-byte reissue)
        long rowb = (long)tn2 * 128;
#pragma unroll
        for (int k = 0; k < 12; k++) {
            int i = tid + k * 128;
            int r = i / 12, c8 = (i % 12) * 8;
            cp_async16(xb[buf] + (uint32_t)(r * XH + c8) * 2u,
                       g_atth + (rowb + r) * 96 + c8);
        }
        CP_COMMIT();
        buf ^= 1;
    }
    CP_WAIT0();
}

// ---------------- full fp16 tensor-core attention (FA2, ldmatrix B-frags) ----
#define QS2 40       // row stride in halfs
#define QSH_B 1024
#define KSH_B (QSH_B + 256 * QS2 * 2)   // 21504
#define VSH_B (KSH_B + 256 * QS2 * 2)   // 41984
#define ATTN_SMEM (VSH_B + 256 * QS2 * 2)  // 62464 bytes

__global__ void __launch_bounds__(256, 2)
attn_mma_kernel() {
    extern __shared__ char smc[];
    int* sidx = (int*)smc;
    __half* qsh = (__half*)(smc + QSH_B);
    __half* ksh = (__half*)(smc + KSH_B);
    __half* vsh = (__half*)(smc + VSH_B);

    int tid = threadIdx.x;
    int lane = tid & 31, wid = tid >> 5;
    int lr = lane >> 2, lc = lane & 3;

    int gb = blockIdx.x;
    int g = gb & 255;
    int hb = gb >> 8;
    int h = hb % HH;
    int b = hb / HH;

    sidx[tid] = g_idx[b * NN + g * GS + tid];
    __syncthreads();

    long base = ((long)(b * HH + h)) * NN;

    for (int i = tid; i < 256 * 4; i += 256) {
        int row = i >> 2, j = i & 3;
        long tk = sidx[row];
        *(uint4*)(qsh + row * QS2 + j * 8) = ((const uint4*)(g_qh + (base + tk) * HD))[j];
        *(uint4*)(ksh + row * QS2 + j * 8) = ((const uint4*)(g_kh + (base + tk) * HD))[j];
        *(uint4*)(vsh + row * QS2 + j * 8) = ((const uint4*)(g_vh + (base + tk) * HD))[j];
    }
    __syncthreads();

    int m0 = wid * 32;

    int tsel = lane >> 3, trow = lane & 7;
    uint32_t kaddr = smem_u32(ksh) +
                     2u * ((((tsel >> 1) * 8 + trow) * QS2) + (tsel & 1) * 8);
    uint32_t vaddr = smem_u32(vsh) +
                     2u * ((((tsel & 1) * 8 + trow) * QS2) + (tsel >> 1) * 8);

    uint32_t qa[2][2][4];
#pragma unroll
    for (int ks = 0; ks < 2; ks++)
#pragma unroll
        for (int mt = 0; mt < 2; mt++) {
            int row = m0 + mt * 16 + lr;
            qa[ks][mt][0] = *(uint32_t*)(qsh + row * QS2 + ks * 16 + 2 * lc);
            qa[ks][mt][1] = *(uint32_t*)(qsh + (row + 8) * QS2 + ks * 16 + 2 * lc);
            qa[ks][mt][2] = *(uint32_t*)(qsh + row * QS2 + ks * 16 + 2 * lc + 8);
            qa[ks][mt][3] = *(uint32_t*)(qsh + (row + 8) * QS2 + ks * 16 + 2 * lc + 8);
        }

    float oacc[2][4][4];
#pragma unroll
    for (int mt = 0; mt < 2; mt++)
#pragma unroll
        for (int nt = 0; nt < 4; nt++)
#pragma unroll
            for (int j = 0; j < 4; j++) oacc[mt][nt][j] = 0.f;
    float rs[4] = {0.f, 0.f, 0.f, 0.f};

#pragma unroll 2
    for (int c = 0; c < 16; c++) {
        uint32_t coff = 2u * (uint32_t)(c * 16 * QS2);

        float sfr[2][2][4];
#pragma unroll
        for (int mt = 0; mt < 2; mt++)
#pragma unroll
            for (int nt = 0; nt < 2; nt++)
#pragma unroll
                for (int j = 0; j < 4; j++) sfr[mt][nt][j] = 0.f;

        uint32_t kb0[4], kb1[4];
        ldsm4(kb0, kaddr + coff);
        ldsm4(kb1, kaddr + coff + 32);
#pragma unroll
        for (int mt = 0; mt < 2; mt++) {
            mma16h(sfr[mt][0], qa[0][mt], kb0[0], kb0[1]);
            mma16h(sfr[mt][1], qa[0][mt], kb0[2], kb0[3]);
            mma16h(sfr[mt][0], qa[1][mt], kb1[0], kb1[1]);
            mma16h(sfr[mt][1], qa[1][mt], kb1[2], kb1[3]);
        }

        uint32_t pa[2][4];
#pragma unroll
        for (int mt = 0; mt < 2; mt++) {
            float e00 = exp2f(sfr[mt][0][0]);
            float e01 = exp2f(sfr[mt][0][1]);
            float e02 = exp2f(sfr[mt][0][2]);
            float e03 = exp2f(sfr[mt][0][3]);
            float e10 = exp2f(sfr[mt][1][0]);
            float e11 = exp2f(sfr[mt][1][1]);
            float e12 = exp2f(sfr[mt][1][2]);
            float e13 = exp2f(sfr[mt][1][3]);
            rs[mt * 2 + 0] += (e00 + e01) + (e10 + e11);
            rs[mt * 2 + 1] += (e02 + e03) + (e12 + e13);
            __half2 h0 = __floats2half2_rn(e00, e01);
            __half2 h1 = __floats2half2_rn(e02, e03);
            __half2 h2 = __floats2half2_rn(e10, e11);
            __half2 h3 = __floats2half2_rn(e12, e13);
            pa[mt][0] = *(uint32_t*)&h0;
            pa[mt][1] = *(uint32_t*)&h1;
            pa[mt][2] = *(uint32_t*)&h2;
            pa[mt][3] = *(uint32_t*)&h3;
        }

        uint32_t vb0[4], vb1[4];
        ldsm4t(vb0, vaddr + coff);
        ldsm4t(vb1, vaddr + coff + 32);
#pragma unroll
        for (int mt = 0; mt < 2; mt++) {
            mma16h(oacc[mt][0], pa[mt], vb0[0], vb0[1]);
            mma16h(oacc[mt][1], pa[mt], vb0[2], vb0[3]);
            mma16h(oacc[mt][2], pa[mt], vb1[0], vb1[1]);
            mma16h(oacc[mt][3], pa[mt], vb1[2], vb1[3]);
        }
    }

#pragma unroll
    for (int r = 0; r < 4; r++) {
        rs[r] += __shfl_xor_sync(0xffffffffu, rs[r], 1);
        rs[r] += __shfl_xor_sync(0xffffffffu, rs[r], 2);
    }

#pragma unroll
    for (int mt = 0; mt < 2; mt++) {
#pragma unroll
        for (int half = 0; half < 2; half++) {
            int row = m0 + mt * 16 + lr + half * 8;
            int tok = sidx[row];
            float inv = 1.f / rs[mt * 2 + half];
            __half* op = g_atth + ((long)b * NN + tok) * CC + h * HD;
#pragma unroll
            for (int nt = 0; nt < 4; nt++) {
                int col = nt * 8 + 2 * lc;
                *(__half2*)(op + col) =
                    __floats2half2_rn(oacc[mt][nt][half * 2 + 0] * inv,
                                      oacc[mt][nt][half * 2 + 1] * inv);
            }
        }
    }
}

// ---------------- launch ------------------------------------------------------
extern "C" void kernel_launch(void* const* d_in, const int* in_sizes, int n_in,
                              void* d_out, int out_size) {
    const float* xq = (const float*)d_in[0];
    const float* xk = (const float*)d_in[1];
    const float* xv = (const float*)d_in[2];
    const float* Wq = (const float*)d_in[3];
    const float* bq = (const float*)d_in[4];
    const float* Wp = (const float*)d_in[5];
    const float* bp = (const float*)d_in[6];
    const int* vor  = (const int*)d_in[7];
    float* out = (float*)d_out;

    cudaFuncSetAttribute(proj_qkv_kernel, cudaFuncAttributeMaxDynamicSharedMemorySize, Q_TOTAL);
    cudaFuncSetAttribute(proj_out_kernel, cudaFuncAttributeMaxDynamicSharedMemorySize, O_TOTAL);
    cudaFuncSetAttribute(attn_mma_kernel, cudaFuncAttributeMaxDynamicSharedMemorySize, ATTN_SMEM);

    const int PGRID = 444;  // 3 CTAs/SM x 148

    // sort
    sortA_kernel<<<256, 256>>>(vor, 0);                               // 0
    sortA_kernel<<<256, 256>>>(vor, 1);                               // 1
    sortB_kernel<<<dim3(256, BB), 256>>>(vor);                        // 2

    // persistent pipelined QKV projection — ncu-profiled slot
    proj_qkv_kernel<<<PGRID, 128, Q_TOTAL>>>(xq, xk, xv, Wq, bq);     // 3

    // fp16 tensor-core attention
    attn_mma_kernel<<<BB * HH * NG, 256, ATTN_SMEM>>>();              // 4

    // persistent pipelined output projection
    proj_out_kernel<<<PGRID, 128, O_TOTAL>>>(Wp, bp, out);            // 5
}

// round 17
// speedup vs baseline: 1.1316x; 1.1316x over previous
#include <cuda_runtime.h>
#include <cuda_fp16.h>
#include <cstdint>

#define BB 2
#define NN 65536
#define CC 96
#define HH 3
#define HD 32
#define NG 256
#define GS 256
// ATTN_SCALE * log2(e): logits pre-scaled so softmax uses exp2 (exact)
#define ATTN_SCALE_LOG2E 0.25503837160174146f

// ---------------- fp16 mma.sync + ldmatrix + cp.async helpers ----------------
__device__ __forceinline__ uint32_t smem_u32(const void* p) {
    uint32_t a;
    asm("{ .reg .u64 t; cvta.to.shared.u64 t, %1; cvt.u32.u64 %0, t; }"
        : "=r"(a) : "l"(p));
    return a;
}
__device__ __forceinline__ void mma16h(float* d, const uint32_t* a, uint32_t b0,
                                       uint32_t b1) {
    asm volatile(
        "mma.sync.aligned.m16n8k16.row.col.f32.f16.f16.f32 "
        "{%0,%1,%2,%3}, {%4,%5,%6,%7}, {%8,%9}, {%0,%1,%2,%3};"
        : "+f"(d[0]), "+f"(d[1]), "+f"(d[2]), "+f"(d[3])
        : "r"(a[0]), "r"(a[1]), "r"(a[2]), "r"(a[3]), "r"(b0), "r"(b1));
}
__device__ __forceinline__ void ldsm4(uint32_t* r, uint32_t addr) {
    asm volatile(
        "ldmatrix.sync.aligned.m8n8.x4.shared.b16 {%0,%1,%2,%3}, [%4];"
        : "=r"(r[0]), "=r"(r[1]), "=r"(r[2]), "=r"(r[3]) : "r"(addr));
}
__device__ __forceinline__ void ldsm4t(uint32_t* r, uint32_t addr) {
    asm volatile(
        "ldmatrix.sync.aligned.m8n8.x4.trans.shared.b16 {%0,%1,%2,%3}, [%4];"
        : "=r"(r[0]), "=r"(r[1]), "=r"(r[2]), "=r"(r[3]) : "r"(addr));
}
__device__ __forceinline__ void cp_async16(uint32_t saddr, const void* gptr) {
    asm volatile("cp.async.ca.shared.global [%0], [%1], 16;"
                 :: "r"(saddr), "l"(gptr));
}
#define CP_COMMIT() asm volatile("cp.async.commit_group;" ::: "memory")
#define CP_WAIT1()  asm volatile("cp.async.wait_group 1;" ::: "memory")
#define CP_WAIT0()  asm volatile("cp.async.wait_group 0;" ::: "memory")

// ---------------- scratch -----------------------------------------------------
static __device__ __half g_qh[(size_t)BB * HH * NN * HD];
static __device__ __half g_kh[(size_t)BB * HH * NN * HD];
static __device__ __half g_vh[(size_t)BB * HH * NN * HD];
static __device__ __half g_atth[(size_t)BB * NN * CC];
static __device__ int    g_idx[(size_t)BB * NN];
static __device__ int    g_cnt2[(size_t)BB * 256 * NG];  // [b][chunk][label]

// ---------------- stable counting sort: atomic-free ---------------------------
__global__ void sortA_kernel(const int* __restrict__ vor, int b) {  // grid 256
    int blk = blockIdx.x;
    int i = threadIdx.x;
    __shared__ int hist[256];
    hist[i] = 0;
    __syncthreads();
    int l = vor[b * NN + blk * 256 + i];
    int g = min(max(l - 1, 0), 255);
    atomicAdd(&hist[g], 1);  // smem only
    __syncthreads();
    g_cnt2[(b * 256 + blk) * NG + i] = hist[i];
}

__global__ void sortB_kernel(const int* __restrict__ vor) {  // grid (256, BB)
    int b = blockIdx.y;
    int blk = blockIdx.x;
    int i = threadIdx.x;
    __shared__ int sc[256];
    __shared__ int offarr[256];
    __shared__ int lab[256];

    int tot = 0, pre = 0;
    const int* cb = g_cnt2 + b * 256 * NG + i;
#pragma unroll 4
    for (int ch = 0; ch < 256; ch++) {
        int c = cb[ch * NG];
        tot += c;
        pre += (ch < blk) ? c : 0;
    }
    sc[i] = tot;
    __syncthreads();
    for (int d = 1; d < 256; d <<= 1) {
        int t = (i >= d) ? sc[i - d] : 0;
        __syncthreads();
        sc[i] += t;
        __syncthreads();
    }
    offarr[i] = (sc[i] - tot) + pre;
    __syncthreads();

    int n = blk * 256 + i;
    int l = vor[b * NN + n];
    int g = min(max(l - 1, 0), 255);
    lab[i] = g;
    __syncthreads();
    int rank = 0;
    for (int j = 0; j < i; j++) rank += (lab[j] == g);
    g_idx[b * NN + offarr[g] + rank] = n;
}

// ---------------- persistent pipelined fp16 projection GEMM ------------------
// (R15-proven configuration: 2 CTAs/SM, 64-row fp32 double stages, 10.4/3.5
// tiles per CTA. R16 showed smaller chunks / bigger grids regress.)
#define XH 104
#define WH 104
#define WBYTES (96 * WH * 2)               // 19968
#define M0_S0  WBYTES                      // stage0: 64x96 fp32 (24576 B)
#define M0_S1  (M0_S0 + 64 * 96 * 4)
#define M0_X   (M0_S1 + 64 * 96 * 4)
#define M0_TOTAL (M0_X + 128 * XH * 2)     // 95744 B
#define M1_X0  WBYTES
#define M1_X1  (M1_X0 + 128 * XH * 2)
#define M1_TOTAL (M1_X1 + 128 * XH * 2)    // 73216 B

__global__ void __launch_bounds__(128)
proj_mma_kernel(const float* __restrict__ x0, const float* __restrict__ x1,
                const float* __restrict__ x2, const float* __restrict__ W,
                const float* __restrict__ bias, float* __restrict__ extout,
                int mode) {
    extern __shared__ char smc[];
    __half* wsm = (__half*)smc;
    __shared__ float bs[96];

    int tid = threadIdx.x;
    int lane = tid & 31, wid = tid >> 5;
    int lr = lane >> 2, lc = lane & 3;

    // ---- W (k-major, UNSCALED) + bias, once per CTA ----
    for (int i = tid; i < 96 * 24; i += 128) {
        int k = i / 24, n4 = (i % 24) * 4;
        float4 v = *(const float4*)(W + k * 96 + n4);
        __half2 h0 = __floats2half2_rn(v.x, v.y);
        __half2 h1 = __floats2half2_rn(v.z, v.w);
        uint2 u;
        u.x = *(uint32_t*)&h0;
        u.y = *(uint32_t*)&h1;
        *(uint2*)(wsm + k * WH + n4) = u;
    }
    if (tid < 96) bs[tid] = bias[tid];

    int m0 = wid * 32;
    int tsel = lane >> 3, trow = lane & 7;
    uint32_t waddr = smem_u32(wsm) +
                     2u * (((tsel & 1) * 8 + trow) * WH + (tsel >> 1) * 8);
    int stride = gridDim.x;

    if (mode == 0) {
        __half* xsm = (__half*)(smc + M0_X);
        uint32_t s0 = smem_u32(smc + M0_S0);
        uint32_t s1 = smem_u32(smc + M0_S1);
        uint32_t xaddr = smem_u32(xsm) +
                         2u * (((tsel & 1) * 8 + trow) * XH + (tsel >> 1) * 8);
        const int nt = 3 * 1024;

        // prologue: both halves of first tile
        {
            int tile = blockIdx.x;
#pragma unroll
            for (int h = 0; h < 2; h++) {
                int sel = tile >> 10;
                const float* xp = (sel == 0) ? x0 : (sel == 1) ? x1 : x2;
                long rowb = (long)(tile & 1023) * 128 + h * 64;
                uint32_t sb = h ? s1 : s0;
#pragma unroll
                for (int k = 0; k < 12; k++) {
                    int i = tid + k * 128;
                    int r = i / 24, c4 = (i % 24) * 4;
                    cp_async16(sb + (uint32_t)(r * 96 + c4) * 4u,
                               xp + (rowb + r) * 96 + c4);
                }
                CP_COMMIT();
            }
        }

        for (int t = blockIdx.x; t < nt; t += stride) {
            int tn = t + stride;
            if (tn >= nt) tn = t;  // clamp: reissues identical bytes (benign)
            __syncthreads();       // xsm free (prev epilogue reads done)

#pragma unroll
            for (int h = 0; h < 2; h++) {
                CP_WAIT1();  // this half's stage ready (own copies)
                const float* stf = (const float*)(smc + (h ? M0_S1 : M0_S0));
#pragma unroll
                for (int k = 0; k < 12; k++) {
                    int i = tid + k * 128;
                    int r = i / 24, c4 = (i % 24) * 4;
                    float4 v = *(const float4*)(stf + r * 96 + c4);
                    __half2 h0 = __floats2half2_rn(v.x, v.y);
                    __half2 h1 = __floats2half2_rn(v.z, v.w);
                    uint2 u;
                    u.x = *(uint32_t*)&h0;
                    u.y = *(uint32_t*)&h1;
                    *(uint2*)(xsm + (h * 64 + r) * XH + c4) = u;
                }
                // prefetch next tile's half h into the same stage
                int sel = tn >> 10;
                const float* xp = (sel == 0) ? x0 : (sel == 1) ? x1 : x2;
                long rowb = (long)(tn & 1023) * 128 + h * 64;
                uint32_t sb = h ? s1 : s0;
#pragma unroll
                for (int k = 0; k < 12; k++) {
                    int i = tid + k * 128;
                    int r = i / 24, c4 = (i % 24) * 4;
                    cp_async16(sb + (uint32_t)(r * 96 + c4) * 4u,
                               xp + (rowb + r) * 96 + c4);
                }
                CP_COMMIT();
            }
            __syncthreads();  // converts visible to all warps

            float acc[2][12][4];
#pragma unroll
            for (int mt = 0; mt < 2; mt++)
#pragma unroll
                for (int nn = 0; nn < 12; nn++)
#pragma unroll
                    for (int j = 0; j < 4; j++) acc[mt][nn][j] = 0.f;
#pragma unroll
            for (int ks = 0; ks < 6; ks++) {
                uint32_t a[2][4];
                ldsm4(a[0], xaddr + 2u * (uint32_t)((m0 + 0) * XH + ks * 16));
                ldsm4(a[1], xaddr + 2u * (uint32_t)((m0 + 16) * XH + ks * 16));
#pragma unroll
                for (int ntp = 0; ntp < 6; ntp++) {
                    uint32_t bf[4];
                    ldsm4t(bf, waddr + 2u * (uint32_t)(ks * 16 * WH + ntp * 16));
                    mma16h(acc[0][2 * ntp], a[0], bf[0], bf[1]);
                    mma16h(acc[0][2 * ntp + 1], a[0], bf[2], bf[3]);
                    mma16h(acc[1][2 * ntp], a[1], bf[0], bf[1]);
                    mma16h(acc[1][2 * ntp + 1], a[1], bf[2], bf[3]);
                }
            }
            __syncthreads();  // all ldmatrix reads of xsm done

            // epilogue: scale applied here (q only), stage in xsm, coalesced
            int selc = t >> 10;
            float sc = (selc == 0) ? ATTN_SCALE_LOG2E : 1.f;
#pragma unroll
            for (int mt = 0; mt < 2; mt++)
#pragma unroll
                for (int half = 0; half < 2; half++) {
                    int row = m0 + mt * 16 + lr + half * 8;
#pragma unroll
                    for (int nn = 0; nn < 12; nn++) {
                        int col = nn * 8 + 2 * lc;
                        *(__half2*)(xsm + row * XH + col) = __floats2half2_rn(
                            (acc[mt][nn][half * 2 + 0] + bs[col]) * sc,
                            (acc[mt][nn][half * 2 + 1] + bs[col + 1]) * sc);
                    }
                }
            __syncthreads();
            __half* dst = (selc == 0) ? g_qh : (selc == 1) ? g_kh : g_vh;
            long row0 = (long)(t & 1023) * 128;
            int bb = (int)(row0 >> 16);
            int part = tid & 3;
            int rbase = tid >> 2;
#pragma unroll
            for (int h = 0; h < 3; h++) {
                __half* hb = dst +
                    ((((long)(bb * HH + h)) * NN + (row0 & (NN - 1))) * HD);
#pragma unroll
                for (int pass = 0; pass < 4; pass++) {
                    int row = pass * 32 + rbase;
                    *(uint4*)(hb + (long)row * HD + part * 8) =
                        *(uint4*)(xsm + row * XH + h * 32 + part * 8);
                }
            }
        }
        CP_WAIT0();
    } else {
        // mode 1: fp16 g_atth -> fp32 extout, double-buffered xsm
        const int nt = 1024;
        uint32_t xb[2] = {smem_u32(smc + M1_X0), smem_u32(smc + M1_X1)};

        // prologue: tiles t0 -> buf0, t0+stride -> buf1
#pragma unroll
        for (int p = 0; p < 2; p++) {
            int tile = blockIdx.x + p * stride;
            if (tile >= nt) tile = blockIdx.x;
            long rowb = (long)tile * 128;
#pragma unroll
            for (int k = 0; k < 12; k++) {
                int i = tid + k * 128;
                int r = i / 12, c8 = (i % 12) * 8;
                cp_async16(xb[p] + (uint32_t)(r * XH + c8) * 2u,
                           g_atth + (rowb + r) * 96 + c8);
            }
            CP_COMMIT();
        }

        int buf = 0;
        for (int t = blockIdx.x; t < nt; t += stride) {
            CP_WAIT1();
            __syncthreads();
            uint32_t xaddr = xb[buf] +
                             2u * (((tsel & 1) * 8 + trow) * XH + (tsel >> 1) * 8);

            float acc[2][12][4];
#pragma unroll
            for (int mt = 0; mt < 2; mt++)
#pragma unroll
                for (int nn = 0; nn < 12; nn++)
#pragma unroll
                    for (int j = 0; j < 4; j++) acc[mt][nn][j] = 0.f;
#pragma unroll
            for (int ks = 0; ks < 6; ks++) {
                uint32_t a[2][4];
                ldsm4(a[0], xaddr + 2u * (uint32_t)((m0 + 0) * XH + ks * 16));
                ldsm4(a[1], xaddr + 2u * (uint32_t)((m0 + 16) * XH + ks * 16));
#pragma unroll
                for (int ntp = 0; ntp < 6; ntp++) {
                    uint32_t bf[4];
                    ldsm4t(bf, waddr + 2u * (uint32_t)(ks * 16 * WH + ntp * 16));
                    mma16h(acc[0][2 * ntp], a[0], bf[0], bf[1]);
                    mma16h(acc[0][2 * ntp + 1], a[0], bf[2], bf[3]);
                    mma16h(acc[1][2 * ntp], a[1], bf[0], bf[1]);
                    mma16h(acc[1][2 * ntp + 1], a[1], bf[2], bf[3]);
                }
            }

            long row0 = (long)t * 128;
#pragma unroll
            for (int mt = 0; mt < 2; mt++)
#pragma unroll
                for (int half = 0; half < 2; half++) {
                    int row = m0 + mt * 16 + lr + half * 8;
                    long gr = row0 + row;
#pragma unroll
                    for (int nn = 0; nn < 12; nn++) {
                        int col = nn * 8 + 2 * lc;
                        *(float2*)(extout + gr * 96 + col) =
                            make_float2(acc[mt][nn][half * 2 + 0] + bs[col],
                                        acc[mt][nn][half * 2 + 1] + bs[col + 1]);
                    }
                }
            __syncthreads();  // all reads of xb[buf] done before refill

            int tn2 = t + 2 * stride;
            if (tn2 >= nt) tn2 = t;  // clamp (identical-byte reissue)
            long rowb = (long)tn2 * 128;
#pragma unroll
            for (int k = 0; k < 12; k++) {
                int i = tid + k * 128;
                int r = i / 12, c8 = (i % 12) * 8;
                cp_async16(xb[buf] + (uint32_t)(r * XH + c8) * 2u,
                           g_atth + (rowb + r) * 96 + c8);
            }
            CP_COMMIT();
            buf ^= 1;
        }
        CP_WAIT0();
    }
}

// ---------------- full fp16 tensor-core attention (FA2, ldmatrix B-frags) ----
// Gather now via cp.async (rows are 64B = 4x16B segments; no reg round-trip).
#define QS2 40       // row stride in halfs
#define QSH_B 1024
#define KSH_B (QSH_B + 256 * QS2 * 2)   // 21504
#define VSH_B (KSH_B + 256 * QS2 * 2)   // 41984
#define ATTN_SMEM (VSH_B + 256 * QS2 * 2)  // 62464 bytes

__global__ void __launch_bounds__(256, 2)
attn_mma_kernel() {
    extern __shared__ char smc[];
    int* sidx = (int*)smc;
    __half* qsh = (__half*)(smc + QSH_B);
    __half* ksh = (__half*)(smc + KSH_B);
    __half* vsh = (__half*)(smc + VSH_B);

    int tid = threadIdx.x;
    int lane = tid & 31, wid = tid >> 5;
    int lr = lane >> 2, lc = lane & 3;

    int gb = blockIdx.x;
    int g = gb & 255;
    int hb = gb >> 8;
    int h = hb % HH;
    int b = hb / HH;

    sidx[tid] = g_idx[b * NN + g * GS + tid];
    __syncthreads();

    long base = ((long)(b * HH + h)) * NN;

    // gather via cp.async: 4 segments x 3 tensors per pair of threads
    uint32_t qsb = smem_u32(qsh), ksb = smem_u32(ksh), vsb = smem_u32(vsh);
    for (int i = tid; i < 256 * 4; i += 256) {
        int row = i >> 2, j = i & 3;
        long tk = sidx[row];
        uint32_t off = (uint32_t)(row * QS2 + j * 8) * 2u;
        const __half* qsrc = g_qh + (base + tk) * HD + j * 8;
        const __half* ksrc = g_kh + (base + tk) * HD + j * 8;
        const __half* vsrc = g_vh + (base + tk) * HD + j * 8;
        cp_async16(qsb + off, qsrc);
        cp_async16(ksb + off, ksrc);
        cp_async16(vsb + off, vsrc);
    }
    CP_COMMIT();
    CP_WAIT0();
    __syncthreads();

    int m0 = wid * 32;

    int tsel = lane >> 3, trow = lane & 7;
    uint32_t kaddr = smem_u32(ksh) +
                     2u * ((((tsel >> 1) * 8 + trow) * QS2) + (tsel & 1) * 8);
    uint32_t vaddr = smem_u32(vsh) +
                     2u * ((((tsel & 1) * 8 + trow) * QS2) + (tsel >> 1) * 8);

    uint32_t qa[2][2][4];
#pragma unroll
    for (int ks = 0; ks < 2; ks++)
#pragma unroll
        for (int mt = 0; mt < 2; mt++) {
            int row = m0 + mt * 16 + lr;
            qa[ks][mt][0] = *(uint32_t*)(qsh + row * QS2 + ks * 16 + 2 * lc);
            qa[ks][mt][1] = *(uint32_t*)(qsh + (row + 8) * QS2 + ks * 16 + 2 * lc);
            qa[ks][mt][2] = *(uint32_t*)(qsh + row * QS2 + ks * 16 + 2 * lc + 8);
            qa[ks][mt][3] = *(uint32_t*)(qsh + (row + 8) * QS2 + ks * 16 + 2 * lc + 8);
        }

    float oacc[2][4][4];
#pragma unroll
    for (int mt = 0; mt < 2; mt++)
#pragma unroll
        for (int nt = 0; nt < 4; nt++)
#pragma unroll
            for (int j = 0; j < 4; j++) oacc[mt][nt][j] = 0.f;
    float rs[4] = {0.f, 0.f, 0.f, 0.f};

#pragma unroll 2
    for (int c = 0; c < 16; c++) {
        uint32_t coff = 2u * (uint32_t)(c * 16 * QS2);

        float sfr[2][2][4];
#pragma unroll
        for (int mt = 0; mt < 2; mt++)
#pragma unroll
            for (int nt = 0; nt < 2; nt++)
#pragma unroll
                for (int j = 0; j < 4; j++) sfr[mt][nt][j] = 0.f;

        uint32_t kb0[4], kb1[4];
        ldsm4(kb0, kaddr + coff);
        ldsm4(kb1, kaddr + coff + 32);
#pragma unroll
        for (int mt = 0; mt < 2; mt++) {
            mma16h(sfr[mt][0], qa[0][mt], kb0[0], kb0[1]);
            mma16h(sfr[mt][1], qa[0][mt], kb0[2], kb0[3]);
            mma16h(sfr[mt][0], qa[1][mt], kb1[0], kb1[1]);
            mma16h(sfr[mt][1], qa[1][mt], kb1[2], kb1[3]);
        }

        uint32_t pa[2][4];
#pragma unroll
        for (int mt = 0; mt < 2; mt++) {
            float e00 = exp2f(sfr[mt][0][0]);
            float e01 = exp2f(sfr[mt][0][1]);
            float e02 = exp2f(sfr[mt][0][2]);
            float e03 = exp2f(sfr[mt][0][3]);
            float e10 = exp2f(sfr[mt][1][0]);
            float e11 = exp2f(sfr[mt][1][1]);
            float e12 = exp2f(sfr[mt][1][2]);
            float e13 = exp2f(sfr[mt][1][3]);
            rs[mt * 2 + 0] += (e00 + e01) + (e10 + e11);
            rs[mt * 2 + 1] += (e02 + e03) + (e12 + e13);
            __half2 h0 = __floats2half2_rn(e00, e01);
            __half2 h1 = __floats2half2_rn(e02, e03);
            __half2 h2 = __floats2half2_rn(e10, e11);
            __half2 h3 = __floats2half2_rn(e12, e13);
            pa[mt][0] = *(uint32_t*)&h0;
            pa[mt][1] = *(uint32_t*)&h1;
            pa[mt][2] = *(uint32_t*)&h2;
            pa[mt][3] = *(uint32_t*)&h3;
        }

        uint32_t vb0[4], vb1[4];
        ldsm4t(vb0, vaddr + coff);
        ldsm4t(vb1, vaddr + coff + 32);
#pragma unroll
        for (int mt = 0; mt < 2; mt++) {
            mma16h(oacc[mt][0], pa[mt], vb0[0], vb0[1]);
            mma16h(oacc[mt][1], pa[mt], vb0[2], vb0[3]);
            mma16h(oacc[mt][2], pa[mt], vb1[0], vb1[1]);
            mma16h(oacc[mt][3], pa[mt], vb1[2], vb1[3]);
        }
    }

#pragma unroll
    for (int r = 0; r < 4; r++) {
        rs[r] += __shfl_xor_sync(0xffffffffu, rs[r], 1);
        rs[r] += __shfl_xor_sync(0xffffffffu, rs[r], 2);
    }

#pragma unroll
    for (int mt = 0; mt < 2; mt++) {
#pragma unroll
        for (int half = 0; half < 2; half++) {
            int row = m0 + mt * 16 + lr + half * 8;
            int tok = sidx[row];
            float inv = 1.f / rs[mt * 2 + half];
            __half* op = g_atth + ((long)b * NN + tok) * CC + h * HD;
#pragma unroll
            for (int nt = 0; nt < 4; nt++) {
                int col = nt * 8 + 2 * lc;
                *(__half2*)(op + col) =
                    __floats2half2_rn(oacc[mt][nt][half * 2 + 0] * inv,
                                      oacc[mt][nt][half * 2 + 1] * inv);
            }
        }
    }
}

// ---------------- launch ------------------------------------------------------
extern "C" void kernel_launch(void* const* d_in, const int* in_sizes, int n_in,
                              void* d_out, int out_size) {
    const float* xq = (const float*)d_in[0];
    const float* xk = (const float*)d_in[1];
    const float* xv = (const float*)d_in[2];
    const float* Wq = (const float*)d_in[3];
    const float* bq = (const float*)d_in[4];
    const float* Wp = (const float*)d_in[5];
    const float* bp = (const float*)d_in[6];
    const int* vor  = (const int*)d_in[7];
    float* out = (float*)d_out;

    cudaFuncSetAttribute(proj_mma_kernel, cudaFuncAttributeMaxDynamicSharedMemorySize, M0_TOTAL);
    cudaFuncSetAttribute(attn_mma_kernel, cudaFuncAttributeMaxDynamicSharedMemorySize, ATTN_SMEM);

    const int PGRID = 296;  // 2 CTAs/SM x 148 (R15-proven point)

    // sort
    sortA_kernel<<<256, 256>>>(vor, 0);                               // 0
    sortA_kernel<<<256, 256>>>(vor, 1);                               // 1
    sortB_kernel<<<dim3(256, BB), 256>>>(vor);                        // 2

    // persistent pipelined QKV projection — ncu-profiled slot
    proj_mma_kernel<<<PGRID, 128, M0_TOTAL>>>(                        // 3
        xq, xk, xv, Wq, bq, nullptr, 0);

    // fp16 tensor-core attention (cp.async gather)
    attn_mma_kernel<<<BB * HH * NG, 256, ATTN_SMEM>>>();              // 4

    // persistent pipelined output projection
    proj_mma_kernel<<<PGRID, 128, M1_TOTAL>>>(                        // 5
        nullptr, nullptr, nullptr, Wp, bp, out, 1);
}